// round 1
// baseline (speedup 1.0000x reference)
#include <cuda_runtime.h>
#include <math_constants.h>

// Problem shape (fixed by the dataset)
#define BB 4
#define HH 32
#define DD 128
#define SS 8192
#define NSPLITS 8
#define NWARPS 4          // warps per split CTA
#define NBH (BB * HH)     // 128

// Scratch for split-KV partials (device globals: allocation-free)
__device__ float g_pm[NBH * NSPLITS];
__device__ float g_pl[NBH * NSPLITS];
__device__ float g_pacc[NBH * NSPLITS * DD];

__device__ __forceinline__ float warp_sum(float v) {
#pragma unroll
    for (int o = 16; o > 0; o >>= 1)
        v += __shfl_xor_sync(0xffffffffu, v, o);
    return v;
}

// ---------------------------------------------------------------------------
// Kernel 1: each CTA = one (b, h, split). Each warp scans positions strided
// by NWARPS inside the split chunk. lane owns dims [4*lane, 4*lane+4).
// ---------------------------------------------------------------------------
__global__ __launch_bounds__(NWARPS * 32)
void attn_split_kernel(const float* __restrict__ x,
                       const float* __restrict__ kv,
                       const int*   __restrict__ cur_pos) {
    const int bid   = blockIdx.x;            // b*H*NSPLITS + h*NSPLITS + split
    const int split = bid % NSPLITS;
    const int bh    = bid / NSPLITS;
    const int h     = bh % HH;
    const int b     = bh / HH;

    const int tid  = threadIdx.x;
    const int lane = tid & 31;
    const int w    = tid >> 5;

    const int len   = *cur_pos + 1;                      // valid positions
    const int chunk = (len + NSPLITS - 1) / NSPLITS;
    const int s0    = split * chunk;
    const int s1    = min(len, s0 + chunk);

    // q[b,0,h,:] — lane's 4 dims
    const float4 q = *reinterpret_cast<const float4*>(
        x + (size_t)(b * HH + h) * DD + lane * 4);
    const float scale = rsqrtf((float)DD);

    const size_t row_stride = (size_t)HH * DD;           // stride over s
    const size_t kv_half    = (size_t)BB * SS * HH * DD; // K->V offset
    const float* Kp = kv + (size_t)b * SS * row_stride + (size_t)h * DD + lane * 4;
    const float* Vp = Kp + kv_half;

    float  m = -CUDART_INF_F;
    float  l = 0.f;
    float4 acc = make_float4(0.f, 0.f, 0.f, 0.f);

    int s = s0 + w;
    // manual 2x unroll: both position loads issued before the serial
    // online-softmax chain -> MLP ~4 per warp
    for (; s + NWARPS < s1; s += 2 * NWARPS) {
        const int sA = s, sB = s + NWARPS;
        const float4 kA = *reinterpret_cast<const float4*>(Kp + (size_t)sA * row_stride);
        const float4 vA = *reinterpret_cast<const float4*>(Vp + (size_t)sA * row_stride);
        const float4 kB = *reinterpret_cast<const float4*>(Kp + (size_t)sB * row_stride);
        const float4 vB = *reinterpret_cast<const float4*>(Vp + (size_t)sB * row_stride);

        float dA = kA.x * q.x + kA.y * q.y + kA.z * q.z + kA.w * q.w;
        dA = warp_sum(dA);
        float dB = kB.x * q.x + kB.y * q.y + kB.z * q.z + kB.w * q.w;
        dB = warp_sum(dB);

        {
            const float sc   = dA * scale;
            const float mn   = fmaxf(m, sc);
            const float corr = __expf(m - mn);
            const float p    = __expf(sc - mn);
            l = l * corr + p;
            acc.x = acc.x * corr + p * vA.x;
            acc.y = acc.y * corr + p * vA.y;
            acc.z = acc.z * corr + p * vA.z;
            acc.w = acc.w * corr + p * vA.w;
            m = mn;
        }
        {
            const float sc   = dB * scale;
            const float mn   = fmaxf(m, sc);
            const float corr = __expf(m - mn);
            const float p    = __expf(sc - mn);
            l = l * corr + p;
            acc.x = acc.x * corr + p * vB.x;
            acc.y = acc.y * corr + p * vB.y;
            acc.z = acc.z * corr + p * vB.z;
            acc.w = acc.w * corr + p * vB.w;
            m = mn;
        }
    }
    for (; s < s1; s += NWARPS) {
        const float4 kk = *reinterpret_cast<const float4*>(Kp + (size_t)s * row_stride);
        const float4 vv = *reinterpret_cast<const float4*>(Vp + (size_t)s * row_stride);
        float d = kk.x * q.x + kk.y * q.y + kk.z * q.z + kk.w * q.w;
        d = warp_sum(d);
        const float sc   = d * scale;
        const float mn   = fmaxf(m, sc);
        const float corr = __expf(m - mn);
        const float p    = __expf(sc - mn);
        l = l * corr + p;
        acc.x = acc.x * corr + p * vv.x;
        acc.y = acc.y * corr + p * vv.y;
        acc.z = acc.z * corr + p * vv.z;
        acc.w = acc.w * corr + p * vv.w;
        m = mn;
    }

    // ---- combine the NWARPS warps of this CTA ----
    __shared__ float sm_m[NWARPS];
    __shared__ float sm_l[NWARPS];
    __shared__ float sm_acc[NWARPS][DD];

    if (lane == 0) { sm_m[w] = m; sm_l[w] = l; }
    sm_acc[w][lane * 4 + 0] = acc.x;
    sm_acc[w][lane * 4 + 1] = acc.y;
    sm_acc[w][lane * 4 + 2] = acc.z;
    sm_acc[w][lane * 4 + 3] = acc.w;
    __syncthreads();

    if (w == 0) {
        float M = -CUDART_INF_F;
#pragma unroll
        for (int i = 0; i < NWARPS; i++) M = fmaxf(M, sm_m[i]);

        float  L = 0.f;
        float4 o = make_float4(0.f, 0.f, 0.f, 0.f);
#pragma unroll
        for (int i = 0; i < NWARPS; i++) {
            if (sm_l[i] == 0.f) continue;   // warp saw no positions
            const float c = __expf(sm_m[i] - M);
            L += c * sm_l[i];
            o.x += c * sm_acc[i][lane * 4 + 0];
            o.y += c * sm_acc[i][lane * 4 + 1];
            o.z += c * sm_acc[i][lane * 4 + 2];
            o.w += c * sm_acc[i][lane * 4 + 3];
        }
        g_pm[bid] = M;
        g_pl[bid] = L;
        float4* pacc = reinterpret_cast<float4*>(g_pacc + (size_t)bid * DD);
        pacc[lane] = o;
    }
}

// ---------------------------------------------------------------------------
// Kernel 2: one CTA per (b, h); 32 threads merge the NSPLITS partials.
// ---------------------------------------------------------------------------
__global__ __launch_bounds__(32)
void attn_combine_kernel(float* __restrict__ out) {
    const int bh   = blockIdx.x;
    const int lane = threadIdx.x;

    float M = -CUDART_INF_F;
#pragma unroll
    for (int i = 0; i < NSPLITS; i++)
        M = fmaxf(M, g_pm[bh * NSPLITS + i]);

    float  L = 0.f;
    float4 o = make_float4(0.f, 0.f, 0.f, 0.f);
#pragma unroll
    for (int i = 0; i < NSPLITS; i++) {
        const int idx = bh * NSPLITS + i;
        const float mi = g_pm[idx];
        if (g_pl[idx] == 0.f) continue;     // empty split
        const float c = __expf(mi - M);
        L += c * g_pl[idx];
        const float4 a = reinterpret_cast<const float4*>(g_pacc + (size_t)idx * DD)[lane];
        o.x += c * a.x; o.y += c * a.y; o.z += c * a.z; o.w += c * a.w;
    }
    const float inv = 1.f / L;
    float4 r = make_float4(o.x * inv, o.y * inv, o.z * inv, o.w * inv);
    reinterpret_cast<float4*>(out + (size_t)bh * DD)[lane] = r;
}

// ---------------------------------------------------------------------------
extern "C" void kernel_launch(void* const* d_in, const int* in_sizes, int n_in,
                              void* d_out, int out_size) {
    // Identify inputs defensively by element count:
    //   x: B*H*D = 16384 fp32, kv: 2*B*S*H*D fp32 (largest), current_pos: 1 int
    const float* x  = nullptr;
    const float* kv = nullptr;
    const int*   cp = nullptr;
    long long best_kv = -1;
    for (int i = 0; i < n_in; i++) {
        if (in_sizes[i] == 1) cp = (const int*)d_in[i];
        else if (in_sizes[i] == BB * HH * DD) x = (const float*)d_in[i];
        else if ((long long)in_sizes[i] > best_kv) {
            best_kv = in_sizes[i];
            kv = (const float*)d_in[i];
        }
    }

    attn_split_kernel<<<NBH * NSPLITS, NWARPS * 32>>>(x, kv, cp);
    attn_combine_kernel<<<NBH, 32>>>((float*)d_out);
}

// round 2
// speedup vs baseline: 1.0380x; 1.0380x over previous
#include <cuda_runtime.h>
#include <math_constants.h>

// Problem shape (fixed by the dataset)
#define BB 4
#define HH 32
#define DD 128
#define SS 8192
#define NSPLITS 8
#define NWARPS 4          // warps per split CTA
#define NBH (BB * HH)     // 128

// Scratch for split-KV partials (device globals: allocation-free)
__device__ float g_pm[NBH * NSPLITS];
__device__ float g_pl[NBH * NSPLITS];
__device__ float g_pacc[NBH * NSPLITS * DD];
__device__ int   g_cnt[NBH];   // zero-init; self-resetting -> graph-replay safe

__device__ __forceinline__ float warp_sum(float v) {
#pragma unroll
    for (int o = 16; o > 0; o >>= 1)
        v += __shfl_xor_sync(0xffffffffu, v, o);
    return v;
}

__device__ __forceinline__ float dot4(const float4 a, const float4 b) {
    return a.x * b.x + a.y * b.y + a.z * b.z + a.w * b.w;
}

// ---------------------------------------------------------------------------
// One CTA = one (b, h, split). Warps stride positions inside the split chunk.
// Lane owns dims [4*lane, 4*lane+4). Combine is fused: the last CTA per (b,h)
// merges all split partials and writes the final output.
// ---------------------------------------------------------------------------
__global__ __launch_bounds__(NWARPS * 32)
void attn_split_kernel(const float* __restrict__ x,
                       const float* __restrict__ kv,
                       const int*   __restrict__ cur_pos,
                       float*       __restrict__ out) {
    const int bid   = blockIdx.x;            // b*H*NSPLITS + h*NSPLITS + split
    const int bh    = bid / NSPLITS;
    const int h     = bh % HH;
    const int b     = bh / HH;
    const int split = bid % NSPLITS;

    const int tid  = threadIdx.x;
    const int lane = tid & 31;
    const int w    = tid >> 5;

    const int len   = *cur_pos + 1;                      // valid positions
    const int chunk = (len + NSPLITS - 1) / NSPLITS;
    const int s0    = split * chunk;
    const int s1    = min(len, s0 + chunk);

    // q[b,0,h,:] — lane's 4 dims
    const float4 q = *reinterpret_cast<const float4*>(
        x + (size_t)(b * HH + h) * DD + lane * 4);
    const float scale = rsqrtf((float)DD);

    const size_t row_stride = (size_t)HH * DD;           // stride over s
    const size_t kv_half    = (size_t)BB * SS * HH * DD; // K->V offset
    const float* Kp = kv + (size_t)b * SS * row_stride + (size_t)h * DD + lane * 4;
    const float* Vp = Kp + kv_half;

    float  m = -CUDART_INF_F;
    float  l = 0.f;
    float4 acc = make_float4(0.f, 0.f, 0.f, 0.f);

    int s = s0 + w;
    // 4x unroll: 8 streaming float4 loads in flight before dependent math,
    // single max/rescale per group -> 4 independent __expf's.
    for (; s + 3 * NWARPS < s1; s += 4 * NWARPS) {
        const float4 k0 = __ldcs(reinterpret_cast<const float4*>(Kp + (size_t)(s            ) * row_stride));
        const float4 v0 = __ldcs(reinterpret_cast<const float4*>(Vp + (size_t)(s            ) * row_stride));
        const float4 k1 = __ldcs(reinterpret_cast<const float4*>(Kp + (size_t)(s +     NWARPS) * row_stride));
        const float4 v1 = __ldcs(reinterpret_cast<const float4*>(Vp + (size_t)(s +     NWARPS) * row_stride));
        const float4 k2 = __ldcs(reinterpret_cast<const float4*>(Kp + (size_t)(s + 2 * NWARPS) * row_stride));
        const float4 v2 = __ldcs(reinterpret_cast<const float4*>(Vp + (size_t)(s + 2 * NWARPS) * row_stride));
        const float4 k3 = __ldcs(reinterpret_cast<const float4*>(Kp + (size_t)(s + 3 * NWARPS) * row_stride));
        const float4 v3 = __ldcs(reinterpret_cast<const float4*>(Vp + (size_t)(s + 3 * NWARPS) * row_stride));

        const float sc0 = warp_sum(dot4(k0, q)) * scale;
        const float sc1 = warp_sum(dot4(k1, q)) * scale;
        const float sc2 = warp_sum(dot4(k2, q)) * scale;
        const float sc3 = warp_sum(dot4(k3, q)) * scale;

        const float mn = fmaxf(fmaxf(fmaxf(m, sc0), fmaxf(sc1, sc2)), sc3);
        const float corr = __expf(m - mn);
        const float p0 = __expf(sc0 - mn);
        const float p1 = __expf(sc1 - mn);
        const float p2 = __expf(sc2 - mn);
        const float p3 = __expf(sc3 - mn);
        m = mn;
        l = l * corr + ((p0 + p1) + (p2 + p3));
        acc.x = acc.x * corr + (p0 * v0.x + p1 * v1.x) + (p2 * v2.x + p3 * v3.x);
        acc.y = acc.y * corr + (p0 * v0.y + p1 * v1.y) + (p2 * v2.y + p3 * v3.y);
        acc.z = acc.z * corr + (p0 * v0.z + p1 * v1.z) + (p2 * v2.z + p3 * v3.z);
        acc.w = acc.w * corr + (p0 * v0.w + p1 * v1.w) + (p2 * v2.w + p3 * v3.w);
    }
    for (; s < s1; s += NWARPS) {
        const float4 kk = __ldcs(reinterpret_cast<const float4*>(Kp + (size_t)s * row_stride));
        const float4 vv = __ldcs(reinterpret_cast<const float4*>(Vp + (size_t)s * row_stride));
        const float sc = warp_sum(dot4(kk, q)) * scale;
        const float mn   = fmaxf(m, sc);
        const float corr = __expf(m - mn);
        const float p    = __expf(sc - mn);
        m = mn;
        l = l * corr + p;
        acc.x = acc.x * corr + p * vv.x;
        acc.y = acc.y * corr + p * vv.y;
        acc.z = acc.z * corr + p * vv.z;
        acc.w = acc.w * corr + p * vv.w;
    }

    // ---- combine the NWARPS warps of this CTA ----
    __shared__ float sm_m[NWARPS];
    __shared__ float sm_l[NWARPS];
    __shared__ float sm_acc[NWARPS][DD];

    if (lane == 0) { sm_m[w] = m; sm_l[w] = l; }
    sm_acc[w][lane * 4 + 0] = acc.x;
    sm_acc[w][lane * 4 + 1] = acc.y;
    sm_acc[w][lane * 4 + 2] = acc.z;
    sm_acc[w][lane * 4 + 3] = acc.w;
    __syncthreads();

    if (w == 0) {
        float M = -CUDART_INF_F;
#pragma unroll
        for (int i = 0; i < NWARPS; i++) M = fmaxf(M, sm_m[i]);

        float  L = 0.f;
        float4 o = make_float4(0.f, 0.f, 0.f, 0.f);
#pragma unroll
        for (int i = 0; i < NWARPS; i++) {
            if (sm_l[i] == 0.f) continue;   // warp saw no positions
            const float c = __expf(sm_m[i] - M);
            L += c * sm_l[i];
            o.x += c * sm_acc[i][lane * 4 + 0];
            o.y += c * sm_acc[i][lane * 4 + 1];
            o.z += c * sm_acc[i][lane * 4 + 2];
            o.w += c * sm_acc[i][lane * 4 + 3];
        }
        g_pm[bid] = M;
        g_pl[bid] = L;
        reinterpret_cast<float4*>(g_pacc + (size_t)bid * DD)[lane] = o;

        // ---- fused cross-split combine: last CTA per (b,h) merges ----
        __threadfence();
        int done = 0;
        if (lane == 0) done = atomicAdd(&g_cnt[bh], 1);
        done = __shfl_sync(0xffffffffu, done, 0);

        if (done == NSPLITS - 1) {
            float GM = -CUDART_INF_F;
#pragma unroll
            for (int i = 0; i < NSPLITS; i++)
                GM = fmaxf(GM, __ldcg(&g_pm[bh * NSPLITS + i]));

            float  GL = 0.f;
            float4 go = make_float4(0.f, 0.f, 0.f, 0.f);
#pragma unroll
            for (int i = 0; i < NSPLITS; i++) {
                const int idx = bh * NSPLITS + i;
                const float li = __ldcg(&g_pl[idx]);
                if (li == 0.f) continue;
                const float c = __expf(__ldcg(&g_pm[idx]) - GM);
                GL += c * li;
                const float4 a = __ldcg(reinterpret_cast<const float4*>(
                    g_pacc + (size_t)idx * DD) + lane);
                go.x += c * a.x; go.y += c * a.y;
                go.z += c * a.z; go.w += c * a.w;
            }
            const float inv = 1.f / GL;
            const float4 r = make_float4(go.x * inv, go.y * inv,
                                         go.z * inv, go.w * inv);
            reinterpret_cast<float4*>(out + (size_t)bh * DD)[lane] = r;

            if (lane == 0) g_cnt[bh] = 0;   // reset for next graph replay
        }
    }
}

// ---------------------------------------------------------------------------
extern "C" void kernel_launch(void* const* d_in, const int* in_sizes, int n_in,
                              void* d_out, int out_size) {
    // Identify inputs defensively by element count:
    //   x: B*H*D = 16384 fp32, kv: 2*B*S*H*D fp32 (largest), current_pos: 1 int
    const float* x  = nullptr;
    const float* kv = nullptr;
    const int*   cp = nullptr;
    long long best_kv = -1;
    for (int i = 0; i < n_in; i++) {
        if (in_sizes[i] == 1) cp = (const int*)d_in[i];
        else if (in_sizes[i] == BB * HH * DD) x = (const float*)d_in[i];
        else if ((long long)in_sizes[i] > best_kv) {
            best_kv = in_sizes[i];
            kv = (const float*)d_in[i];
        }
    }

    attn_split_kernel<<<NBH * NSPLITS, NWARPS * 32>>>(x, kv, cp, (float*)d_out);
}